// round 1
// baseline (speedup 1.0000x reference)
#include <cuda_runtime.h>

// Problem constants
#define NB 128
#define NC 10
#define NR 8192
#define NI 8
#define NO 16

// Tiling
#define BPB 64        // b covered per block (2 per thread: lane and lane+32)
#define RB  128       // r per block
#define NTHREADS 320  // 32 lanes x 10 warps (warp == capsule class c)

// Scratch (no cudaMalloc allowed)
__device__ float g_s[3][NB * NC * NO];     // per-pass s accumulators
__device__ float g_Vsum[NB * NC * NO];     // running sum of v vectors

__global__ void zero_s_kernel() {
    int idx = blockIdx.x * blockDim.x + threadIdx.x;
    if (idx < 3 * NB * NC * NO) (&g_s[0][0])[idx] = 0.0f;
}

// One routing pass. T==0: uniform weights 0.1 (softmax of zeros).
// T>0: logits a = u . Vsum  (routing logits are linear in v, so the
// accumulated b_ij equals u . (v0 + v1 + ...)).
template <int T>
__global__ __launch_bounds__(NTHREADS, 1) void pass_kernel(
    const float* __restrict__ x,   // [B,R,I]
    const float* __restrict__ W,   // [C,R,I,O]
    int slot)
{
    __shared__ float sm_e[2][NC][BPB];   // exp(a) exchange, double-buffered

    const int lane = threadIdx.x & 31;
    const int c    = threadIdx.x >> 5;        // warp id == class
    const int b0   = blockIdx.y * BPB + lane; // this thread: b0 and b0+32
    const int r0   = blockIdx.x * RB;

    float V[2][NO];
    if (T > 0) {
        #pragma unroll
        for (int bp = 0; bp < 2; bp++) {
            const float4* vp =
                (const float4*)&g_Vsum[(((size_t)(b0 + bp * 32)) * NC + c) * NO];
            #pragma unroll
            for (int q = 0; q < 4; q++) {
                float4 v = __ldg(vp + q);
                V[bp][q * 4 + 0] = v.x;
                V[bp][q * 4 + 1] = v.y;
                V[bp][q * 4 + 2] = v.z;
                V[bp][q * 4 + 3] = v.w;
            }
        }
    }

    float sacc[2][NO];
    #pragma unroll
    for (int bp = 0; bp < 2; bp++)
        #pragma unroll
        for (int o = 0; o < NO; o++) sacc[bp][o] = 0.0f;

    // W row base for this warp's class c
    const float4* Wp = (const float4*)(W + ((size_t)c * NR + r0) * (NI * NO));

    for (int rr = 0; rr < RB; rr++) {
        // x[b, r, :]  (8 floats per b, 2 b's)
        float xv[2][NI];
        #pragma unroll
        for (int bp = 0; bp < 2; bp++) {
            const float4* xp = (const float4*)(
                x + (((size_t)(b0 + bp * 32)) * NR + (r0 + rr)) * NI);
            float4 xa = __ldg(xp);
            float4 xb = __ldg(xp + 1);
            xv[bp][0] = xa.x; xv[bp][1] = xa.y; xv[bp][2] = xa.z; xv[bp][3] = xa.w;
            xv[bp][4] = xb.x; xv[bp][5] = xb.y; xv[bp][6] = xb.z; xv[bp][7] = xb.w;
        }

        // u[b, c, r, :] = sum_i x[b,r,i] * W[c,r,i,:]
        float u[2][NO];
        #pragma unroll
        for (int bp = 0; bp < 2; bp++)
            #pragma unroll
            for (int o = 0; o < NO; o++) u[bp][o] = 0.0f;

        const float4* wrow = Wp + rr * 32;   // 128 floats = 32 float4 per r
        #pragma unroll
        for (int k = 0; k < 32; k++) {
            float4 w4 = __ldg(wrow + k);     // warp-uniform -> broadcast
            const int i  = k >> 2;
            const int ob = (k & 3) * 4;
            #pragma unroll
            for (int bp = 0; bp < 2; bp++) {
                u[bp][ob + 0] = fmaf(xv[bp][i], w4.x, u[bp][ob + 0]);
                u[bp][ob + 1] = fmaf(xv[bp][i], w4.y, u[bp][ob + 1]);
                u[bp][ob + 2] = fmaf(xv[bp][i], w4.z, u[bp][ob + 2]);
                u[bp][ob + 3] = fmaf(xv[bp][i], w4.w, u[bp][ob + 3]);
            }
        }

        float w[2];
        if (T == 0) {
            w[0] = 0.1f;
            w[1] = 0.1f;
        } else {
            const int p = rr & 1;
            float e_loc[2];
            #pragma unroll
            for (int bp = 0; bp < 2; bp++) {
                float a = 0.0f;
                #pragma unroll
                for (int o = 0; o < NO; o++) a = fmaf(u[bp][o], V[bp][o], a);
                e_loc[bp] = __expf(a);
                sm_e[p][c][lane + bp * 32] = e_loc[bp];
            }
            __syncthreads();
            #pragma unroll
            for (int bp = 0; bp < 2; bp++) {
                float Z = 0.0f;
                #pragma unroll
                for (int cc = 0; cc < NC; cc++) Z += sm_e[p][cc][lane + bp * 32];
                w[bp] = __fdividef(e_loc[bp], Z);
            }
        }

        #pragma unroll
        for (int bp = 0; bp < 2; bp++)
            #pragma unroll
            for (int o = 0; o < NO; o++)
                sacc[bp][o] = fmaf(w[bp], u[bp][o], sacc[bp][o]);
    }

    float* s_out = &g_s[slot][0];
    #pragma unroll
    for (int bp = 0; bp < 2; bp++) {
        float* sp = s_out + (((size_t)(b0 + bp * 32)) * NC + c) * NO;
        #pragma unroll
        for (int o = 0; o < NO; o++) atomicAdd(sp + o, sacc[bp][o]);
    }
}

// squash(s) -> v.  mode 0: Vsum = v ; mode 1: Vsum += v ; mode 2: out = v
__global__ void squash_kernel(int slot, float* __restrict__ out, int mode) {
    int idx = blockIdx.x * blockDim.x + threadIdx.x;
    if (idx >= NB * NC) return;

    const float* s = &g_s[slot][idx * NO];
    float sv[NO];
    float sq = 0.0f;
    #pragma unroll
    for (int q = 0; q < 4; q++) {
        float4 v = *(const float4*)(s + q * 4);
        sv[q * 4 + 0] = v.x; sv[q * 4 + 1] = v.y;
        sv[q * 4 + 2] = v.z; sv[q * 4 + 3] = v.w;
        sq += v.x * v.x + v.y * v.y + v.z * v.z + v.w * v.w;
    }
    float scale = (sq / (1.0f + sq)) * rsqrtf(sq + 1e-8f);

    if (mode == 0) {
        #pragma unroll
        for (int o = 0; o < NO; o++) g_Vsum[idx * NO + o] = scale * sv[o];
    } else if (mode == 1) {
        #pragma unroll
        for (int o = 0; o < NO; o++) g_Vsum[idx * NO + o] += scale * sv[o];
    } else {
        #pragma unroll
        for (int o = 0; o < NO; o++) out[idx * NO + o] = scale * sv[o];
    }
}

extern "C" void kernel_launch(void* const* d_in, const int* in_sizes, int n_in,
                              void* d_out, int out_size) {
    const float* x = (const float*)d_in[0];   // [128, 8192, 8]
    const float* W = (const float*)d_in[1];   // [10, 8192, 8, 16]
    float* out = (float*)d_out;               // [128, 10, 16]

    dim3 grid(NR / RB, NB / BPB);             // (64, 2)
    dim3 sq_grid((NB * NC + 255) / 256);

    zero_s_kernel<<<(3 * NB * NC * NO + 255) / 256, 256>>>();

    // Pass 0: uniform weights (softmax of zeros) -> s0, v0
    pass_kernel<0><<<grid, NTHREADS>>>(x, W, 0);
    squash_kernel<<<sq_grid, 256>>>(0, out, 0);      // Vsum = v0

    // Pass 1: logits = u . v0 -> s1, v1
    pass_kernel<1><<<grid, NTHREADS>>>(x, W, 1);
    squash_kernel<<<sq_grid, 256>>>(1, out, 1);      // Vsum += v1

    // Pass 2: logits = u . (v0 + v1) -> s2, v2 = output
    pass_kernel<2><<<grid, NTHREADS>>>(x, W, 2);
    squash_kernel<<<sq_grid, 256>>>(2, out, 2);      // out = v2
}

// round 2
// speedup vs baseline: 1.0010x; 1.0010x over previous
#include <cuda_runtime.h>

// Problem constants
#define NB 128
#define NC 10
#define NR 8192
#define NI 8
#define NO 16

// Tiling
#define BPB 64        // b covered per block (2 per thread: lane and lane+32)
#define RB  128       // r per block
#define NTHREADS 320  // 32 lanes x 10 warps (warp == capsule class c)

// Scratch (no cudaMalloc allowed)
__device__ float g_s[3][NB * NC * NO];     // per-pass s accumulators
__device__ float g_Vsum[NB * NC * NO];     // running sum of v vectors

__global__ void zero_s_kernel() {
    int idx = blockIdx.x * blockDim.x + threadIdx.x;
    if (idx < 3 * NB * NC * NO) (&g_s[0][0])[idx] = 0.0f;
}

// One routing pass. T==0: uniform weights 0.1 (softmax of zeros).
// T>0: logits a = u . Vsum  (routing logits are linear in v, so the
// accumulated b_ij equals u . (v0 + v1 + ...)).
template <int T>
__global__ __launch_bounds__(NTHREADS, 1) void pass_kernel(
    const float* __restrict__ x,   // [B,R,I]
    const float* __restrict__ W,   // [C,R,I,O]
    int slot)
{
    __shared__ float sm_e[2][NC][BPB];   // exp(a) exchange, double-buffered

    const int lane = threadIdx.x & 31;
    const int c    = threadIdx.x >> 5;        // warp id == class
    const int b0   = blockIdx.y * BPB + lane; // this thread: b0 and b0+32
    const int r0   = blockIdx.x * RB;

    float V[2][NO];
    if (T > 0) {
        #pragma unroll
        for (int bp = 0; bp < 2; bp++) {
            const float4* vp =
                (const float4*)&g_Vsum[(((size_t)(b0 + bp * 32)) * NC + c) * NO];
            #pragma unroll
            for (int q = 0; q < 4; q++) {
                float4 v = __ldg(vp + q);
                V[bp][q * 4 + 0] = v.x;
                V[bp][q * 4 + 1] = v.y;
                V[bp][q * 4 + 2] = v.z;
                V[bp][q * 4 + 3] = v.w;
            }
        }
    }

    float sacc[2][NO];
    #pragma unroll
    for (int bp = 0; bp < 2; bp++)
        #pragma unroll
        for (int o = 0; o < NO; o++) sacc[bp][o] = 0.0f;

    // W row base for this warp's class c
    const float4* Wp = (const float4*)(W + ((size_t)c * NR + r0) * (NI * NO));

    for (int rr = 0; rr < RB; rr++) {
        // x[b, r, :]  (8 floats per b, 2 b's)
        float xv[2][NI];
        #pragma unroll
        for (int bp = 0; bp < 2; bp++) {
            const float4* xp = (const float4*)(
                x + (((size_t)(b0 + bp * 32)) * NR + (r0 + rr)) * NI);
            float4 xa = __ldg(xp);
            float4 xb = __ldg(xp + 1);
            xv[bp][0] = xa.x; xv[bp][1] = xa.y; xv[bp][2] = xa.z; xv[bp][3] = xa.w;
            xv[bp][4] = xb.x; xv[bp][5] = xb.y; xv[bp][6] = xb.z; xv[bp][7] = xb.w;
        }

        // u[b, c, r, :] = sum_i x[b,r,i] * W[c,r,i,:]
        float u[2][NO];
        #pragma unroll
        for (int bp = 0; bp < 2; bp++)
            #pragma unroll
            for (int o = 0; o < NO; o++) u[bp][o] = 0.0f;

        const float4* wrow = Wp + rr * 32;   // 128 floats = 32 float4 per r
        #pragma unroll
        for (int k = 0; k < 32; k++) {
            float4 w4 = __ldg(wrow + k);     // warp-uniform -> broadcast
            const int i  = k >> 2;
            const int ob = (k & 3) * 4;
            #pragma unroll
            for (int bp = 0; bp < 2; bp++) {
                u[bp][ob + 0] = fmaf(xv[bp][i], w4.x, u[bp][ob + 0]);
                u[bp][ob + 1] = fmaf(xv[bp][i], w4.y, u[bp][ob + 1]);
                u[bp][ob + 2] = fmaf(xv[bp][i], w4.z, u[bp][ob + 2]);
                u[bp][ob + 3] = fmaf(xv[bp][i], w4.w, u[bp][ob + 3]);
            }
        }

        float w[2];
        if (T == 0) {
            w[0] = 0.1f;
            w[1] = 0.1f;
        } else {
            const int p = rr & 1;
            float e_loc[2];
            #pragma unroll
            for (int bp = 0; bp < 2; bp++) {
                float a = 0.0f;
                #pragma unroll
                for (int o = 0; o < NO; o++) a = fmaf(u[bp][o], V[bp][o], a);
                e_loc[bp] = __expf(a);
                sm_e[p][c][lane + bp * 32] = e_loc[bp];
            }
            __syncthreads();
            #pragma unroll
            for (int bp = 0; bp < 2; bp++) {
                float Z = 0.0f;
                #pragma unroll
                for (int cc = 0; cc < NC; cc++) Z += sm_e[p][cc][lane + bp * 32];
                w[bp] = __fdividef(e_loc[bp], Z);
            }
        }

        #pragma unroll
        for (int bp = 0; bp < 2; bp++)
            #pragma unroll
            for (int o = 0; o < NO; o++)
                sacc[bp][o] = fmaf(w[bp], u[bp][o], sacc[bp][o]);
    }

    float* s_out = &g_s[slot][0];
    #pragma unroll
    for (int bp = 0; bp < 2; bp++) {
        float* sp = s_out + (((size_t)(b0 + bp * 32)) * NC + c) * NO;
        #pragma unroll
        for (int o = 0; o < NO; o++) atomicAdd(sp + o, sacc[bp][o]);
    }
}

// squash(s) -> v.  mode 0: Vsum = v ; mode 1: Vsum += v ; mode 2: out = v
__global__ void squash_kernel(int slot, float* __restrict__ out, int mode) {
    int idx = blockIdx.x * blockDim.x + threadIdx.x;
    if (idx >= NB * NC) return;

    const float* s = &g_s[slot][idx * NO];
    float sv[NO];
    float sq = 0.0f;
    #pragma unroll
    for (int q = 0; q < 4; q++) {
        float4 v = *(const float4*)(s + q * 4);
        sv[q * 4 + 0] = v.x; sv[q * 4 + 1] = v.y;
        sv[q * 4 + 2] = v.z; sv[q * 4 + 3] = v.w;
        sq += v.x * v.x + v.y * v.y + v.z * v.z + v.w * v.w;
    }
    float scale = (sq / (1.0f + sq)) * rsqrtf(sq + 1e-8f);

    if (mode == 0) {
        #pragma unroll
        for (int o = 0; o < NO; o++) g_Vsum[idx * NO + o] = scale * sv[o];
    } else if (mode == 1) {
        #pragma unroll
        for (int o = 0; o < NO; o++) g_Vsum[idx * NO + o] += scale * sv[o];
    } else {
        #pragma unroll
        for (int o = 0; o < NO; o++) out[idx * NO + o] = scale * sv[o];
    }
}

extern "C" void kernel_launch(void* const* d_in, const int* in_sizes, int n_in,
                              void* d_out, int out_size) {
    const float* x = (const float*)d_in[0];   // [128, 8192, 8]
    const float* W = (const float*)d_in[1];   // [10, 8192, 8, 16]
    float* out = (float*)d_out;               // [128, 10, 16]

    dim3 grid(NR / RB, NB / BPB);             // (64, 2)
    dim3 sq_grid((NB * NC + 255) / 256);

    zero_s_kernel<<<(3 * NB * NC * NO + 255) / 256, 256>>>();

    // Pass 0: uniform weights (softmax of zeros) -> s0, v0
    pass_kernel<0><<<grid, NTHREADS>>>(x, W, 0);
    squash_kernel<<<sq_grid, 256>>>(0, out, 0);      // Vsum = v0

    // Pass 1: logits = u . v0 -> s1, v1
    pass_kernel<1><<<grid, NTHREADS>>>(x, W, 1);
    squash_kernel<<<sq_grid, 256>>>(1, out, 1);      // Vsum += v1

    // Pass 2: logits = u . (v0 + v1) -> s2, v2 = output
    pass_kernel<2><<<grid, NTHREADS>>>(x, W, 2);
    squash_kernel<<<sq_grid, 256>>>(2, out, 2);      // out = v2
}

// round 3
// speedup vs baseline: 1.3675x; 1.3662x over previous
#include <cuda_runtime.h>
#include <cuda_fp16.h>

// Problem constants
#define NB 128
#define NC 10
#define NR 8192
#define NI 8
#define NO 16

// Tiling
#define BPB 64        // b covered per block (2 per thread)
#define RB  128       // r per block
#define RCH 16        // r chunk staged in smem (pass0)
#define NTHREADS 320  // 32 lanes x 10 warps (warp == capsule class c)

// Scratch (no cudaMalloc allowed)
__device__ float g_s[3][NB * NC * NO];     // per-pass s accumulators
__device__ float g_Vsum[NB * NC * NO];     // running sum of v vectors
// u_hat in fp16: layout [c][r][o8][b][8 halves] as uint4 (8 halves = 16B)
// uint4 index = ((c*NR + r)*2 + o8)*NB + b
__device__ uint4 g_u4[(size_t)NC * NR * 2 * NB];   // 336 MB

__global__ void zero_s_kernel() {
    int idx = blockIdx.x * blockDim.x + threadIdx.x;
    if (idx < 3 * NB * NC * NO) (&g_s[0][0])[idx] = 0.0f;
}

__device__ __forceinline__ uint4 pack8(const float* u) {
    __half2 h0 = __floats2half2_rn(u[0], u[1]);
    __half2 h1 = __floats2half2_rn(u[2], u[3]);
    __half2 h2 = __floats2half2_rn(u[4], u[5]);
    __half2 h3 = __floats2half2_rn(u[6], u[7]);
    uint4 v;
    v.x = *reinterpret_cast<unsigned int*>(&h0);
    v.y = *reinterpret_cast<unsigned int*>(&h1);
    v.z = *reinterpret_cast<unsigned int*>(&h2);
    v.w = *reinterpret_cast<unsigned int*>(&h3);
    return v;
}

__device__ __forceinline__ __half2 u2h(unsigned int v) {
    __half2 h;
    *reinterpret_cast<unsigned int*>(&h) = v;
    return h;
}

// ---------------------------------------------------------------------------
// Pass 0: compute u = einsum('bri,crio->bcro') on the fly (fp32), write u to
// global fp16, accumulate s0 = 0.1 * sum_r u (uniform softmax(0) weights).
// x staged in swizzled smem so all 10 warps share one coalesced load.
// ---------------------------------------------------------------------------
__global__ __launch_bounds__(NTHREADS, 1) void pass0_kernel(
    const float* __restrict__ x,   // [B,R,I]
    const float* __restrict__ W)   // [C,R,I,O]
{
    // x tile: [f = rr*2+h][b] float4, swizzled: idx4 = f*64 + (b ^ (f&7))
    __shared__ float4 xs[32 * 64];   // 32 KB

    const int lane = threadIdx.x & 31;
    const int c    = threadIdx.x >> 5;
    const int b0   = blockIdx.y * BPB + lane;   // global b for bp=0
    const int r0   = blockIdx.x * RB;

    float sacc[2][NO];
    #pragma unroll
    for (int bp = 0; bp < 2; bp++)
        #pragma unroll
        for (int o = 0; o < NO; o++) sacc[bp][o] = 0.0f;

    for (int ch = 0; ch < RB / RCH; ch++) {
        const int rbase = r0 + ch * RCH;
        __syncthreads();   // protect previous chunk's reads
        // Cooperative coalesced load: 64 b x 16 r x 8 i = 2048 float4
        for (int i = threadIdx.x; i < 64 * 32; i += NTHREADS) {
            int b = i >> 5;        // local b 0..63
            int f = i & 31;        // rr*2 + h
            float4 v = __ldg((const float4*)x +
                             ((size_t)(blockIdx.y * BPB + b) * NR + rbase) * 2 + f);
            xs[f * 64 + (b ^ (f & 7))] = v;
        }
        __syncthreads();

        #pragma unroll 1
        for (int rr = 0; rr < RCH; rr++) {
            const int r = rbase + rr;

            float xv[2][NI];
            #pragma unroll
            for (int bp = 0; bp < 2; bp++) {
                #pragma unroll
                for (int h = 0; h < 2; h++) {
                    int f = rr * 2 + h;
                    float4 v = xs[f * 64 + ((lane + bp * 32) ^ (f & 7))];
                    xv[bp][h * 4 + 0] = v.x;
                    xv[bp][h * 4 + 1] = v.y;
                    xv[bp][h * 4 + 2] = v.z;
                    xv[bp][h * 4 + 3] = v.w;
                }
            }

            float u[2][NO];
            #pragma unroll
            for (int bp = 0; bp < 2; bp++)
                #pragma unroll
                for (int o = 0; o < NO; o++) u[bp][o] = 0.0f;

            const float4* wrow = (const float4*)W + ((size_t)c * NR + r) * 32;
            #pragma unroll
            for (int k = 0; k < 32; k++) {
                float4 w4 = __ldg(wrow + k);   // warp-uniform broadcast
                const int i  = k >> 2;
                const int ob = (k & 3) * 4;
                #pragma unroll
                for (int bp = 0; bp < 2; bp++) {
                    u[bp][ob + 0] = fmaf(xv[bp][i], w4.x, u[bp][ob + 0]);
                    u[bp][ob + 1] = fmaf(xv[bp][i], w4.y, u[bp][ob + 1]);
                    u[bp][ob + 2] = fmaf(xv[bp][i], w4.z, u[bp][ob + 2]);
                    u[bp][ob + 3] = fmaf(xv[bp][i], w4.w, u[bp][ob + 3]);
                }
            }

            #pragma unroll
            for (int bp = 0; bp < 2; bp++) {
                size_t base4 = (((size_t)c * NR + r) * 2) * NB + (b0 + bp * 32);
                g_u4[base4]      = pack8(&u[bp][0]);
                g_u4[base4 + NB] = pack8(&u[bp][8]);
                #pragma unroll
                for (int o = 0; o < NO; o++) sacc[bp][o] += u[bp][o];
            }
        }
    }

    float* s_out = &g_s[0][0];
    #pragma unroll
    for (int bp = 0; bp < 2; bp++) {
        float* sp = s_out + (((size_t)(b0 + bp * 32)) * NC + c) * NO;
        #pragma unroll
        for (int o = 0; o < NO; o++) atomicAdd(sp + o, 0.1f * sacc[bp][o]);
    }
}

// ---------------------------------------------------------------------------
// Passes 1/2: stream u (fp16) from global, logits a = u . Vsum (HFMA2),
// softmax across the 10 warps via smem, accumulate s in fp32.
// ---------------------------------------------------------------------------
__global__ __launch_bounds__(NTHREADS, 1) void pass12_kernel(int slot)
{
    __shared__ float sm_e[2][NC][BPB];

    const int lane = threadIdx.x & 31;
    const int c    = threadIdx.x >> 5;
    const int b0   = blockIdx.y * BPB + lane;
    const int r0   = blockIdx.x * RB;

    // V in half2 (for logit dot) — 8 half2 per bp
    __half2 Vh[2][8];
    #pragma unroll
    for (int bp = 0; bp < 2; bp++) {
        const float4* vp =
            (const float4*)&g_Vsum[(((size_t)(b0 + bp * 32)) * NC + c) * NO];
        #pragma unroll
        for (int q = 0; q < 4; q++) {
            float4 v = __ldg(vp + q);
            Vh[bp][q * 2 + 0] = __floats2half2_rn(v.x, v.y);
            Vh[bp][q * 2 + 1] = __floats2half2_rn(v.z, v.w);
        }
    }

    float sacc[2][NO];
    #pragma unroll
    for (int bp = 0; bp < 2; bp++)
        #pragma unroll
        for (int o = 0; o < NO; o++) sacc[bp][o] = 0.0f;

    const size_t cbase = ((size_t)c * NR + r0) * 2 * NB;   // uint4 units

    // prefetch rr = 0
    uint4 q[2][2];
    #pragma unroll
    for (int bp = 0; bp < 2; bp++) {
        size_t i0 = cbase + (b0 + bp * 32);
        q[bp][0] = __ldg(&g_u4[i0]);
        q[bp][1] = __ldg(&g_u4[i0 + NB]);
    }

    #pragma unroll 1
    for (int rr = 0; rr < RB; rr++) {
        // prefetch next r (dummy re-load on last iter)
        const int rn = (rr + 1 < RB) ? rr + 1 : rr;
        uint4 qn[2][2];
        #pragma unroll
        for (int bp = 0; bp < 2; bp++) {
            size_t i0 = cbase + (size_t)rn * (2 * NB) + (b0 + bp * 32);
            qn[bp][0] = __ldg(&g_u4[i0]);
            qn[bp][1] = __ldg(&g_u4[i0 + NB]);
        }

        const int p = rr & 1;
        float e_loc[2];
        #pragma unroll
        for (int bp = 0; bp < 2; bp++) {
            __half2 acc = __hmul2(u2h(q[bp][0].x), Vh[bp][0]);
            acc = __hfma2(u2h(q[bp][0].y), Vh[bp][1], acc);
            acc = __hfma2(u2h(q[bp][0].z), Vh[bp][2], acc);
            acc = __hfma2(u2h(q[bp][0].w), Vh[bp][3], acc);
            acc = __hfma2(u2h(q[bp][1].x), Vh[bp][4], acc);
            acc = __hfma2(u2h(q[bp][1].y), Vh[bp][5], acc);
            acc = __hfma2(u2h(q[bp][1].z), Vh[bp][6], acc);
            acc = __hfma2(u2h(q[bp][1].w), Vh[bp][7], acc);
            float2 af = __half22float2(acc);
            float a = af.x + af.y;
            e_loc[bp] = __expf(a);
            sm_e[p][c][lane + bp * 32] = e_loc[bp];
        }
        __syncthreads();

        #pragma unroll
        for (int bp = 0; bp < 2; bp++) {
            float Z = 0.0f;
            #pragma unroll
            for (int cc = 0; cc < NC; cc++) Z += sm_e[p][cc][lane + bp * 32];
            const float w = __fdividef(e_loc[bp], Z);

            unsigned int raw[8] = {q[bp][0].x, q[bp][0].y, q[bp][0].z, q[bp][0].w,
                                   q[bp][1].x, q[bp][1].y, q[bp][1].z, q[bp][1].w};
            #pragma unroll
            for (int k = 0; k < 8; k++) {
                float2 f = __half22float2(u2h(raw[k]));
                sacc[bp][2 * k + 0] = fmaf(w, f.x, sacc[bp][2 * k + 0]);
                sacc[bp][2 * k + 1] = fmaf(w, f.y, sacc[bp][2 * k + 1]);
            }
        }

        #pragma unroll
        for (int bp = 0; bp < 2; bp++) {
            q[bp][0] = qn[bp][0];
            q[bp][1] = qn[bp][1];
        }
    }

    float* s_out = &g_s[slot][0];
    #pragma unroll
    for (int bp = 0; bp < 2; bp++) {
        float* sp = s_out + (((size_t)(b0 + bp * 32)) * NC + c) * NO;
        #pragma unroll
        for (int o = 0; o < NO; o++) atomicAdd(sp + o, sacc[bp][o]);
    }
}

// squash(s) -> v.  mode 0: Vsum = v ; mode 1: Vsum += v ; mode 2: out = v
__global__ void squash_kernel(int slot, float* __restrict__ out, int mode) {
    int idx = blockIdx.x * blockDim.x + threadIdx.x;
    if (idx >= NB * NC) return;

    const float* s = &g_s[slot][idx * NO];
    float sv[NO];
    float sq = 0.0f;
    #pragma unroll
    for (int q = 0; q < 4; q++) {
        float4 v = *(const float4*)(s + q * 4);
        sv[q * 4 + 0] = v.x; sv[q * 4 + 1] = v.y;
        sv[q * 4 + 2] = v.z; sv[q * 4 + 3] = v.w;
        sq += v.x * v.x + v.y * v.y + v.z * v.z + v.w * v.w;
    }
    float scale = (sq / (1.0f + sq)) * rsqrtf(sq + 1e-8f);

    if (mode == 0) {
        #pragma unroll
        for (int o = 0; o < NO; o++) g_Vsum[idx * NO + o] = scale * sv[o];
    } else if (mode == 1) {
        #pragma unroll
        for (int o = 0; o < NO; o++) g_Vsum[idx * NO + o] += scale * sv[o];
    } else {
        #pragma unroll
        for (int o = 0; o < NO; o++) out[idx * NO + o] = scale * sv[o];
    }
}

extern "C" void kernel_launch(void* const* d_in, const int* in_sizes, int n_in,
                              void* d_out, int out_size) {
    const float* x = (const float*)d_in[0];   // [128, 8192, 8]
    const float* W = (const float*)d_in[1];   // [10, 8192, 8, 16]
    float* out = (float*)d_out;               // [128, 10, 16]

    dim3 grid(NR / RB, NB / BPB);             // (64, 2)
    dim3 sq_grid((NB * NC + 255) / 256);

    zero_s_kernel<<<(3 * NB * NC * NO + 255) / 256, 256>>>();

    // Pass 0: uniform weights; compute u, store fp16, s0 = 0.1*sum u
    pass0_kernel<<<grid, NTHREADS>>>(x, W);
    squash_kernel<<<sq_grid, 256>>>(0, out, 0);      // Vsum = v0

    // Pass 1: logits = u . v0
    pass12_kernel<<<grid, NTHREADS>>>(1);
    squash_kernel<<<sq_grid, 256>>>(1, out, 1);      // Vsum += v1

    // Pass 2: logits = u . (v0 + v1)
    pass12_kernel<<<grid, NTHREADS>>>(2);
    squash_kernel<<<sq_grid, 256>>>(2, out, 2);      // out = v2
}

// round 4
// speedup vs baseline: 3.3715x; 2.4654x over previous
#include <cuda_runtime.h>
#include <cuda_fp16.h>
#include <cstdint>

// Problem constants
#define NB 128
#define NC 10
#define NR 8192
#define NI 8
#define NO 16

#define RCH 64        // r per staged chunk
#define CHUNKS 2      // chunks per block
#define NTHREADS 320  // 10 warps, warp == class c

// Scratch (no cudaMalloc allowed)
__device__ float g_s[3][NB * NC * NO];
__device__ float g_Vsum[NB * NC * NO];
__device__ uint4 g_xh[(size_t)NB * NR];        // x fp16: [b][r][8i]  (16B each)
__device__ uint4 g_wht[(size_t)NC * NR * NO];  // W fp16 transposed: [c][r][o][8i]

__global__ void zero_s_kernel() {
    int idx = blockIdx.x * blockDim.x + threadIdx.x;
    if (idx < 3 * NB * NC * NO) (&g_s[0][0])[idx] = 0.0f;
}

// x [B,R,I] f32 -> g_xh fp16
__global__ void conv_x_kernel(const float* __restrict__ x) {
    int idx = blockIdx.x * blockDim.x + threadIdx.x;   // over NB*NR
    if (idx >= NB * NR) return;
    const float4* p = (const float4*)x + (size_t)idx * 2;
    float4 a = __ldg(p), b = __ldg(p + 1);
    __half2 h0 = __floats2half2_rn(a.x, a.y);
    __half2 h1 = __floats2half2_rn(a.z, a.w);
    __half2 h2 = __floats2half2_rn(b.x, b.y);
    __half2 h3 = __floats2half2_rn(b.z, b.w);
    uint4 v;
    v.x = *(unsigned*)&h0; v.y = *(unsigned*)&h1;
    v.z = *(unsigned*)&h2; v.w = *(unsigned*)&h3;
    g_xh[idx] = v;
}

// W [C,R,I,O] f32 -> g_wht fp16 [C,R,O,I]
__global__ void conv_w_kernel(const float* __restrict__ W) {
    int idx = blockIdx.x * blockDim.x + threadIdx.x;   // over NC*NR*NO
    if (idx >= NC * NR * NO) return;
    int o = idx & 15;
    int rc = idx >> 4;                                  // c*NR + r
    const float* base = W + (size_t)rc * (NI * NO) + o;
    __half h[8];
    #pragma unroll
    for (int i = 0; i < NI; i++) h[i] = __float2half(__ldg(base + i * NO));
    uint4 v;
    v.x = *(unsigned*)&h[0]; v.y = *(unsigned*)&h[2];
    v.z = *(unsigned*)&h[4]; v.w = *(unsigned*)&h[6];
    g_wht[idx] = v;
}

__device__ __forceinline__ void mma_16n8k8(float d[4], unsigned a0, unsigned a1,
                                           unsigned b0) {
    float z = 0.0f;
    asm volatile(
        "mma.sync.aligned.m16n8k8.row.col.f32.f16.f16.f32 "
        "{%0,%1,%2,%3}, {%4,%5}, {%6}, {%7,%8,%9,%10};\n"
        : "=f"(d[0]), "=f"(d[1]), "=f"(d[2]), "=f"(d[3])
        : "r"(a0), "r"(a1), "r"(b0), "f"(z), "f"(z), "f"(z), "f"(z));
}

// ---------------------------------------------------------------------------
// One routing pass, fused: u recomputed via mma.m16n8k8 per (c, r, 32 b's).
// PASS==0: weights 0.1 (softmax of zeros). PASS>0: logits = u . Vsum.
// Warp = class c; warp covers 32 b's (2 m-tiles), all 16 o (2 n-tiles).
// ---------------------------------------------------------------------------
template <int PASS>
__global__ __launch_bounds__(NTHREADS, 2) void pass_kernel()
{
    __shared__ uint4 xs[RCH * 32];          // x tile [r][b] swizzled (32 KB)
    __shared__ float sm_e[NC][32];
    __shared__ float sm_rz[32];

    const int tid  = threadIdx.x;
    const int lane = tid & 31;
    const int c    = tid >> 5;
    const int b0   = blockIdx.x * 32;
    const int gr   = lane >> 2;             // group row 0..7
    const int gc   = lane & 3;              // group col 0..3

    // V values this lane needs (pass > 0): V[b][c][o] at D-fragment positions
    float2 V2[2][2][2];
    if (PASS > 0) {
        #pragma unroll
        for (int mt = 0; mt < 2; mt++)
            #pragma unroll
            for (int ab = 0; ab < 2; ab++)
                #pragma unroll
                for (int t = 0; t < 2; t++) {
                    int b = b0 + mt * 16 + gr + ab * 8;
                    int o = t * 8 + 2 * gc;
                    V2[mt][ab][t] = __ldg((const float2*)
                        &g_Vsum[((size_t)b * NC + c) * NO + o]);
                }
    }

    float sacc[2][2][4];
    #pragma unroll
    for (int mt = 0; mt < 2; mt++)
        #pragma unroll
        for (int t = 0; t < 2; t++)
            #pragma unroll
            for (int j = 0; j < 4; j++) sacc[mt][t][j] = 0.0f;

    const unsigned xs_base = (unsigned)__cvta_generic_to_shared(xs);

    for (int cc = 0; cc < CHUNKS; cc++) {
        const int r0 = (blockIdx.y * CHUNKS + cc) * RCH;

        __syncthreads();
        for (int i = tid; i < 32 * RCH; i += NTHREADS) {
            int b = i / RCH, r = i % RCH;
            xs[r * 32 + (b ^ (r & 7))] =
                __ldg(&g_xh[(size_t)(b0 + b) * NR + r0 + r]);
        }
        __syncthreads();

        #pragma unroll 1
        for (int rr = 0; rr < RCH; rr++) {
            const int r = r0 + rr;

            // A fragments for both 16-row m-tiles: one ldmatrix.x4
            unsigned amat = xs_base + (unsigned)(rr * 32 + (lane ^ (rr & 7))) * 16;
            unsigned ra0, ra1, ra2, ra3;
            asm volatile(
                "ldmatrix.sync.aligned.m8n8.x4.shared.b16 {%0,%1,%2,%3}, [%4];\n"
                : "=r"(ra0), "=r"(ra1), "=r"(ra2), "=r"(ra3) : "r"(amat));

            // B fragments (k8 x n8, two n-tiles): coalesced 128B warp loads
            const unsigned* wb =
                (const unsigned*)(g_wht + ((size_t)c * NR + r) * NO);
            unsigned rb0 = __ldg(&wb[gr * 4 + gc]);
            unsigned rb1 = __ldg(&wb[(gr + 8) * 4 + gc]);

            float d[2][2][4];
            mma_16n8k8(d[0][0], ra0, ra1, rb0);
            mma_16n8k8(d[0][1], ra0, ra1, rb1);
            mma_16n8k8(d[1][0], ra2, ra3, rb0);
            mma_16n8k8(d[1][1], ra2, ra3, rb1);

            if (PASS == 0) {
                #pragma unroll
                for (int mt = 0; mt < 2; mt++)
                    #pragma unroll
                    for (int t = 0; t < 2; t++)
                        #pragma unroll
                        for (int j = 0; j < 4; j++)
                            sacc[mt][t][j] += d[mt][t][j];
            } else {
                // logits: a[b] = u . V  (partial per lane, reduce over quad)
                float a[2][2];
                #pragma unroll
                for (int mt = 0; mt < 2; mt++) {
                    a[mt][0] = d[mt][0][0] * V2[mt][0][0].x
                             + d[mt][0][1] * V2[mt][0][0].y
                             + d[mt][1][0] * V2[mt][0][1].x
                             + d[mt][1][1] * V2[mt][0][1].y;
                    a[mt][1] = d[mt][0][2] * V2[mt][1][0].x
                             + d[mt][0][3] * V2[mt][1][0].y
                             + d[mt][1][2] * V2[mt][1][1].x
                             + d[mt][1][3] * V2[mt][1][1].y;
                }
                #pragma unroll
                for (int mt = 0; mt < 2; mt++)
                    #pragma unroll
                    for (int ab = 0; ab < 2; ab++) {
                        a[mt][ab] += __shfl_xor_sync(0xffffffffu, a[mt][ab], 1);
                        a[mt][ab] += __shfl_xor_sync(0xffffffffu, a[mt][ab], 2);
                    }

                float e[2][2];
                #pragma unroll
                for (int mt = 0; mt < 2; mt++)
                    #pragma unroll
                    for (int ab = 0; ab < 2; ab++)
                        e[mt][ab] = __expf(a[mt][ab]);

                if (gc == 0) {
                    #pragma unroll
                    for (int mt = 0; mt < 2; mt++)
                        #pragma unroll
                        for (int ab = 0; ab < 2; ab++)
                            sm_e[c][mt * 16 + gr + ab * 8] = e[mt][ab];
                }
                __syncthreads();

                if (tid < 32) {
                    float Z = 0.0f;
                    #pragma unroll
                    for (int k = 0; k < NC; k++) Z += sm_e[k][tid];
                    sm_rz[tid] = __fdividef(1.0f, Z);
                }
                __syncthreads();

                float w[2][2];
                #pragma unroll
                for (int mt = 0; mt < 2; mt++)
                    #pragma unroll
                    for (int ab = 0; ab < 2; ab++)
                        w[mt][ab] = e[mt][ab] * sm_rz[mt * 16 + gr + ab * 8];

                #pragma unroll
                for (int mt = 0; mt < 2; mt++)
                    #pragma unroll
                    for (int t = 0; t < 2; t++) {
                        sacc[mt][t][0] = fmaf(w[mt][0], d[mt][t][0], sacc[mt][t][0]);
                        sacc[mt][t][1] = fmaf(w[mt][0], d[mt][t][1], sacc[mt][t][1]);
                        sacc[mt][t][2] = fmaf(w[mt][1], d[mt][t][2], sacc[mt][t][2]);
                        sacc[mt][t][3] = fmaf(w[mt][1], d[mt][t][3], sacc[mt][t][3]);
                    }
            }
        }
    }

    const float scale = (PASS == 0) ? 0.1f : 1.0f;
    float* s = &g_s[PASS][0];
    #pragma unroll
    for (int mt = 0; mt < 2; mt++)
        #pragma unroll
        for (int t = 0; t < 2; t++) {
            int bA = b0 + mt * 16 + gr;
            int o  = t * 8 + 2 * gc;
            atomicAdd(&s[((size_t)bA * NC + c) * NO + o],     scale * sacc[mt][t][0]);
            atomicAdd(&s[((size_t)bA * NC + c) * NO + o + 1], scale * sacc[mt][t][1]);
            atomicAdd(&s[((size_t)(bA + 8) * NC + c) * NO + o],     scale * sacc[mt][t][2]);
            atomicAdd(&s[((size_t)(bA + 8) * NC + c) * NO + o + 1], scale * sacc[mt][t][3]);
        }
}

// squash(s) -> v.  mode 0: Vsum = v ; mode 1: Vsum += v ; mode 2: out = v
__global__ void squash_kernel(int slot, float* __restrict__ out, int mode) {
    int idx = blockIdx.x * blockDim.x + threadIdx.x;
    if (idx >= NB * NC) return;

    const float* s = &g_s[slot][idx * NO];
    float sv[NO];
    float sq = 0.0f;
    #pragma unroll
    for (int q = 0; q < 4; q++) {
        float4 v = *(const float4*)(s + q * 4);
        sv[q * 4 + 0] = v.x; sv[q * 4 + 1] = v.y;
        sv[q * 4 + 2] = v.z; sv[q * 4 + 3] = v.w;
        sq += v.x * v.x + v.y * v.y + v.z * v.z + v.w * v.w;
    }
    float scale = (sq / (1.0f + sq)) * rsqrtf(sq + 1e-8f);

    if (mode == 0) {
        #pragma unroll
        for (int o = 0; o < NO; o++) g_Vsum[idx * NO + o] = scale * sv[o];
    } else if (mode == 1) {
        #pragma unroll
        for (int o = 0; o < NO; o++) g_Vsum[idx * NO + o] += scale * sv[o];
    } else {
        #pragma unroll
        for (int o = 0; o < NO; o++) out[idx * NO + o] = scale * sv[o];
    }
}

extern "C" void kernel_launch(void* const* d_in, const int* in_sizes, int n_in,
                              void* d_out, int out_size) {
    const float* x = (const float*)d_in[0];   // [128, 8192, 8]
    const float* W = (const float*)d_in[1];   // [10, 8192, 8, 16]
    float* out = (float*)d_out;               // [128, 10, 16]

    conv_x_kernel<<<(NB * NR + 255) / 256, 256>>>(x);
    conv_w_kernel<<<(NC * NR * NO + 255) / 256, 256>>>(W);
    zero_s_kernel<<<(3 * NB * NC * NO + 255) / 256, 256>>>();

    dim3 grid(NB / 32, NR / (RCH * CHUNKS));  // (4, 64) = 256 blocks
    dim3 sq_grid((NB * NC + 255) / 256);

    pass_kernel<0><<<grid, NTHREADS>>>();
    squash_kernel<<<sq_grid, 256>>>(0, out, 0);      // Vsum = v0

    pass_kernel<1><<<grid, NTHREADS>>>();
    squash_kernel<<<sq_grid, 256>>>(1, out, 1);      // Vsum += v1

    pass_kernel<2><<<grid, NTHREADS>>>();
    squash_kernel<<<sq_grid, 256>>>(2, out, 2);      // out = v2
}

// round 5
// speedup vs baseline: 3.9562x; 1.1734x over previous
#include <cuda_runtime.h>
#include <cuda_fp16.h>
#include <cstdint>

// Problem constants
#define NB 128
#define NC 10
#define NR 8192
#define NI 8
#define NO 16

#define RCH 64        // r per staged chunk
#define CHUNKS 2      // chunks per block
#define NTHREADS 320  // 10 warps, warp == class c

// Scratch (no cudaMalloc allowed)
__device__ float g_s[3][NB * NC * NO];
__device__ float g_Vsum[NB * NC * NO];
__device__ uint4 g_xh[(size_t)NB * NR];         // x fp16: [b][r][8i]
// W fragments pre-packed per (c, r, lane): .x = B-frag word n-tile0, .y = n-tile1
__device__ uint2 g_wht2[(size_t)NC * NR * 32];

__global__ void zero_s_kernel() {
    int idx = blockIdx.x * blockDim.x + threadIdx.x;
    if (idx < 3 * NB * NC * NO) (&g_s[0][0])[idx] = 0.0f;
}

// x [B,R,I] f32 -> g_xh fp16
__global__ void conv_x_kernel(const float* __restrict__ x) {
    int idx = blockIdx.x * blockDim.x + threadIdx.x;   // over NB*NR
    if (idx >= NB * NR) return;
    const float4* p = (const float4*)x + (size_t)idx * 2;
    float4 a = __ldg(p), b = __ldg(p + 1);
    __half2 h0 = __floats2half2_rn(a.x, a.y);
    __half2 h1 = __floats2half2_rn(a.z, a.w);
    __half2 h2 = __floats2half2_rn(b.x, b.y);
    __half2 h3 = __floats2half2_rn(b.z, b.w);
    uint4 v;
    v.x = *(unsigned*)&h0; v.y = *(unsigned*)&h1;
    v.z = *(unsigned*)&h2; v.w = *(unsigned*)&h3;
    g_xh[idx] = v;
}

// W [C,R,I,O] f32 -> per-lane packed B fragments.
// lane = gr*4+gc: word0 = halves (i=2gc, 2gc+1) at o=gr; word1 = same at o=gr+8.
__global__ void conv_w_kernel(const float* __restrict__ W) {
    int idx = blockIdx.x * blockDim.x + threadIdx.x;   // over NC*NR*32
    if (idx >= NC * NR * 32) return;
    int lane = idx & 31;
    int rc   = idx >> 5;                               // c*NR + r
    int gr = lane >> 2, gc = lane & 3;
    const float* base = W + (size_t)rc * (NI * NO);
    float a0 = __ldg(base + (2 * gc) * NO + gr);
    float a1 = __ldg(base + (2 * gc + 1) * NO + gr);
    float b0 = __ldg(base + (2 * gc) * NO + gr + 8);
    float b1 = __ldg(base + (2 * gc + 1) * NO + gr + 8);
    __half2 h0 = __floats2half2_rn(a0, a1);
    __half2 h1 = __floats2half2_rn(b0, b1);
    uint2 v;
    v.x = *(unsigned*)&h0;
    v.y = *(unsigned*)&h1;
    g_wht2[idx] = v;
}

__device__ __forceinline__ void mma_16n8k8(float d[4], unsigned a0, unsigned a1,
                                           unsigned b0) {
    float z = 0.0f;
    asm volatile(
        "mma.sync.aligned.m16n8k8.row.col.f32.f16.f16.f32 "
        "{%0,%1,%2,%3}, {%4,%5}, {%6}, {%7,%8,%9,%10};\n"
        : "=f"(d[0]), "=f"(d[1]), "=f"(d[2]), "=f"(d[3])
        : "r"(a0), "r"(a1), "r"(b0), "f"(z), "f"(z), "f"(z), "f"(z));
}

__device__ __forceinline__ void mma_16n8k8_acc(float d[4], unsigned a0,
                                               unsigned a1, unsigned b0) {
    asm volatile(
        "mma.sync.aligned.m16n8k8.row.col.f32.f16.f16.f32 "
        "{%0,%1,%2,%3}, {%4,%5}, {%6}, {%0,%1,%2,%3};\n"
        : "+f"(d[0]), "+f"(d[1]), "+f"(d[2]), "+f"(d[3])
        : "r"(a0), "r"(a1), "r"(b0));
}

// ---------------------------------------------------------------------------
// Pass 0: uniform weights -> s0 = 0.1 * sum_r u. Pure MMA accumulation,
// r unrolled x4 for MLP/ILP, accumulators live in the MMA C operand.
// ---------------------------------------------------------------------------
__global__ __launch_bounds__(NTHREADS, 2) void pass0_kernel()
{
    __shared__ uint4 xs[RCH * 32];          // x tile [r][b] swizzled (32 KB)

    const int tid  = threadIdx.x;
    const int lane = tid & 31;
    const int c    = tid >> 5;
    const int b0   = blockIdx.x * 32;
    const int gr   = lane >> 2;
    const int gc   = lane & 3;

    float sacc[2][2][4];
    #pragma unroll
    for (int mt = 0; mt < 2; mt++)
        #pragma unroll
        for (int t = 0; t < 2; t++)
            #pragma unroll
            for (int j = 0; j < 4; j++) sacc[mt][t][j] = 0.0f;

    const unsigned xs_base = (unsigned)__cvta_generic_to_shared(xs);
    const uint2* wbc = g_wht2 + (size_t)c * NR * 32;

    for (int cc = 0; cc < CHUNKS; cc++) {
        const int r0 = (blockIdx.y * CHUNKS + cc) * RCH;

        __syncthreads();
        for (int i = tid; i < 32 * RCH; i += NTHREADS) {
            int b = i / RCH, r = i % RCH;
            xs[r * 32 + (b ^ (r & 7))] =
                __ldg(&g_xh[(size_t)(b0 + b) * NR + r0 + r]);
        }
        __syncthreads();

        #pragma unroll 1
        for (int rr = 0; rr < RCH; rr += 4) {
            unsigned ra[4][4];
            uint2 rbv[4];
            #pragma unroll
            for (int j = 0; j < 4; j++) {
                const int rj = rr + j;
                unsigned amat =
                    xs_base + (unsigned)(rj * 32 + (lane ^ (rj & 7))) * 16;
                asm volatile(
                    "ldmatrix.sync.aligned.m8n8.x4.shared.b16 "
                    "{%0,%1,%2,%3}, [%4];\n"
                    : "=r"(ra[j][0]), "=r"(ra[j][1]),
                      "=r"(ra[j][2]), "=r"(ra[j][3]) : "r"(amat));
                rbv[j] = __ldg(&wbc[(size_t)(r0 + rj) * 32 + lane]);
            }
            #pragma unroll
            for (int j = 0; j < 4; j++) {
                mma_16n8k8_acc(sacc[0][0], ra[j][0], ra[j][1], rbv[j].x);
                mma_16n8k8_acc(sacc[0][1], ra[j][0], ra[j][1], rbv[j].y);
                mma_16n8k8_acc(sacc[1][0], ra[j][2], ra[j][3], rbv[j].x);
                mma_16n8k8_acc(sacc[1][1], ra[j][2], ra[j][3], rbv[j].y);
            }
        }
    }

    float* s = &g_s[0][0];
    #pragma unroll
    for (int mt = 0; mt < 2; mt++)
        #pragma unroll
        for (int t = 0; t < 2; t++) {
            int bA = b0 + mt * 16 + gr;
            int o  = t * 8 + 2 * gc;
            atomicAdd(&s[((size_t)bA * NC + c) * NO + o],     0.1f * sacc[mt][t][0]);
            atomicAdd(&s[((size_t)bA * NC + c) * NO + o + 1], 0.1f * sacc[mt][t][1]);
            atomicAdd(&s[((size_t)(bA + 8) * NC + c) * NO + o],     0.1f * sacc[mt][t][2]);
            atomicAdd(&s[((size_t)(bA + 8) * NC + c) * NO + o + 1], 0.1f * sacc[mt][t][3]);
        }
}

// ---------------------------------------------------------------------------
// Passes 1/2: u recomputed (MMA), logits = u . Vsum, softmax over the 10
// c-warps. r unrolled x2: one barrier pair serves two r's.
// ---------------------------------------------------------------------------
template <int PASS>
__global__ __launch_bounds__(NTHREADS, 2) void pass_kernel()
{
    __shared__ uint4 xs[RCH * 32];
    __shared__ float sm_e[2][NC][32];
    __shared__ float sm_rz[2][32];

    const int tid  = threadIdx.x;
    const int lane = tid & 31;
    const int c    = tid >> 5;
    const int b0   = blockIdx.x * 32;
    const int gr   = lane >> 2;
    const int gc   = lane & 3;

    float2 V2[2][2][2];
    #pragma unroll
    for (int mt = 0; mt < 2; mt++)
        #pragma unroll
        for (int ab = 0; ab < 2; ab++)
            #pragma unroll
            for (int t = 0; t < 2; t++) {
                int b = b0 + mt * 16 + gr + ab * 8;
                int o = t * 8 + 2 * gc;
                V2[mt][ab][t] = __ldg((const float2*)
                    &g_Vsum[((size_t)b * NC + c) * NO + o]);
            }

    float sacc[2][2][4];
    #pragma unroll
    for (int mt = 0; mt < 2; mt++)
        #pragma unroll
        for (int t = 0; t < 2; t++)
            #pragma unroll
            for (int j = 0; j < 4; j++) sacc[mt][t][j] = 0.0f;

    const unsigned xs_base = (unsigned)__cvta_generic_to_shared(xs);
    const uint2* wbc = g_wht2 + (size_t)c * NR * 32;

    for (int cc = 0; cc < CHUNKS; cc++) {
        const int r0 = (blockIdx.y * CHUNKS + cc) * RCH;

        __syncthreads();
        for (int i = tid; i < 32 * RCH; i += NTHREADS) {
            int b = i / RCH, r = i % RCH;
            xs[r * 32 + (b ^ (r & 7))] =
                __ldg(&g_xh[(size_t)(b0 + b) * NR + r0 + r]);
        }
        __syncthreads();

        #pragma unroll 1
        for (int rr = 0; rr < RCH; rr += 2) {
            unsigned ra[2][4];
            uint2 rbv[2];
            #pragma unroll
            for (int j = 0; j < 2; j++) {
                const int rj = rr + j;
                unsigned amat =
                    xs_base + (unsigned)(rj * 32 + (lane ^ (rj & 7))) * 16;
                asm volatile(
                    "ldmatrix.sync.aligned.m8n8.x4.shared.b16 "
                    "{%0,%1,%2,%3}, [%4];\n"
                    : "=r"(ra[j][0]), "=r"(ra[j][1]),
                      "=r"(ra[j][2]), "=r"(ra[j][3]) : "r"(amat));
                rbv[j] = __ldg(&wbc[(size_t)(r0 + rj) * 32 + lane]);
            }

            float d[2][2][2][4];   // [j][mt][t][frag]
            #pragma unroll
            for (int j = 0; j < 2; j++) {
                mma_16n8k8(d[j][0][0], ra[j][0], ra[j][1], rbv[j].x);
                mma_16n8k8(d[j][0][1], ra[j][0], ra[j][1], rbv[j].y);
                mma_16n8k8(d[j][1][0], ra[j][2], ra[j][3], rbv[j].x);
                mma_16n8k8(d[j][1][1], ra[j][2], ra[j][3], rbv[j].y);
            }

            // logits + exp for both r's
            float e[2][2][2];      // [j][mt][ab]
            #pragma unroll
            for (int j = 0; j < 2; j++) {
                float a[2][2];
                #pragma unroll
                for (int mt = 0; mt < 2; mt++) {
                    a[mt][0] = d[j][mt][0][0] * V2[mt][0][0].x
                             + d[j][mt][0][1] * V2[mt][0][0].y
                             + d[j][mt][1][0] * V2[mt][0][1].x
                             + d[j][mt][1][1] * V2[mt][0][1].y;
                    a[mt][1] = d[j][mt][0][2] * V2[mt][1][0].x
                             + d[j][mt][0][3] * V2[mt][1][0].y
                             + d[j][mt][1][2] * V2[mt][1][1].x
                             + d[j][mt][1][3] * V2[mt][1][1].y;
                }
                #pragma unroll
                for (int mt = 0; mt < 2; mt++)
                    #pragma unroll
                    for (int ab = 0; ab < 2; ab++) {
                        a[mt][ab] += __shfl_xor_sync(0xffffffffu, a[mt][ab], 1);
                        a[mt][ab] += __shfl_xor_sync(0xffffffffu, a[mt][ab], 2);
                        e[j][mt][ab] = __expf(a[mt][ab]);
                    }
            }

            if (gc == 0) {
                #pragma unroll
                for (int j = 0; j < 2; j++)
                    #pragma unroll
                    for (int mt = 0; mt < 2; mt++)
                        #pragma unroll
                        for (int ab = 0; ab < 2; ab++)
                            sm_e[j][c][mt * 16 + gr + ab * 8] = e[j][mt][ab];
            }
            __syncthreads();

            if (tid < 64) {
                int j = tid >> 5, bb = tid & 31;
                float Z = 0.0f;
                #pragma unroll
                for (int k = 0; k < NC; k++) Z += sm_e[j][k][bb];
                sm_rz[j][bb] = __fdividef(1.0f, Z);
            }
            __syncthreads();

            #pragma unroll
            for (int j = 0; j < 2; j++) {
                float w[2][2];
                #pragma unroll
                for (int mt = 0; mt < 2; mt++)
                    #pragma unroll
                    for (int ab = 0; ab < 2; ab++)
                        w[mt][ab] = e[j][mt][ab] * sm_rz[j][mt * 16 + gr + ab * 8];

                #pragma unroll
                for (int mt = 0; mt < 2; mt++)
                    #pragma unroll
                    for (int t = 0; t < 2; t++) {
                        sacc[mt][t][0] = fmaf(w[mt][0], d[j][mt][t][0], sacc[mt][t][0]);
                        sacc[mt][t][1] = fmaf(w[mt][0], d[j][mt][t][1], sacc[mt][t][1]);
                        sacc[mt][t][2] = fmaf(w[mt][1], d[j][mt][t][2], sacc[mt][t][2]);
                        sacc[mt][t][3] = fmaf(w[mt][1], d[j][mt][t][3], sacc[mt][t][3]);
                    }
            }
        }
    }

    float* s = &g_s[PASS][0];
    #pragma unroll
    for (int mt = 0; mt < 2; mt++)
        #pragma unroll
        for (int t = 0; t < 2; t++) {
            int bA = b0 + mt * 16 + gr;
            int o  = t * 8 + 2 * gc;
            atomicAdd(&s[((size_t)bA * NC + c) * NO + o],     sacc[mt][t][0]);
            atomicAdd(&s[((size_t)bA * NC + c) * NO + o + 1], sacc[mt][t][1]);
            atomicAdd(&s[((size_t)(bA + 8) * NC + c) * NO + o],     sacc[mt][t][2]);
            atomicAdd(&s[((size_t)(bA + 8) * NC + c) * NO + o + 1], sacc[mt][t][3]);
        }
}

// squash(s) -> v.  mode 0: Vsum = v ; mode 1: Vsum += v ; mode 2: out = v
__global__ void squash_kernel(int slot, float* __restrict__ out, int mode) {
    int idx = blockIdx.x * blockDim.x + threadIdx.x;
    if (idx >= NB * NC) return;

    const float* s = &g_s[slot][idx * NO];
    float sv[NO];
    float sq = 0.0f;
    #pragma unroll
    for (int q = 0; q < 4; q++) {
        float4 v = *(const float4*)(s + q * 4);
        sv[q * 4 + 0] = v.x; sv[q * 4 + 1] = v.y;
        sv[q * 4 + 2] = v.z; sv[q * 4 + 3] = v.w;
        sq += v.x * v.x + v.y * v.y + v.z * v.z + v.w * v.w;
    }
    float scale = (sq / (1.0f + sq)) * rsqrtf(sq + 1e-8f);

    if (mode == 0) {
        #pragma unroll
        for (int o = 0; o < NO; o++) g_Vsum[idx * NO + o] = scale * sv[o];
    } else if (mode == 1) {
        #pragma unroll
        for (int o = 0; o < NO; o++) g_Vsum[idx * NO + o] += scale * sv[o];
    } else {
        #pragma unroll
        for (int o = 0; o < NO; o++) out[idx * NO + o] = scale * sv[o];
    }
}

extern "C" void kernel_launch(void* const* d_in, const int* in_sizes, int n_in,
                              void* d_out, int out_size) {
    const float* x = (const float*)d_in[0];   // [128, 8192, 8]
    const float* W = (const float*)d_in[1];   // [10, 8192, 8, 16]
    float* out = (float*)d_out;               // [128, 10, 16]

    conv_x_kernel<<<(NB * NR + 255) / 256, 256>>>(x);
    conv_w_kernel<<<(NC * NR * 32 + 255) / 256, 256>>>(W);
    zero_s_kernel<<<(3 * NB * NC * NO + 255) / 256, 256>>>();

    dim3 grid(NB / 32, NR / (RCH * CHUNKS));  // (4, 64) = 256 blocks
    dim3 sq_grid((NB * NC + 255) / 256);

    pass0_kernel<<<grid, NTHREADS>>>();
    squash_kernel<<<sq_grid, 256>>>(0, out, 0);      // Vsum = v0

    pass_kernel<1><<<grid, NTHREADS>>>();
    squash_kernel<<<sq_grid, 256>>>(1, out, 1);      // Vsum += v1

    pass_kernel<2><<<grid, NTHREADS>>>();
    squash_kernel<<<sq_grid, 256>>>(2, out, 2);      // out = v2
}